// round 3
// baseline (speedup 1.0000x reference)
#include <cuda_runtime.h>
#include <cstdint>

#define N_USERS 200000
#define N_SPOTS 50000
#define N_NODES (N_USERS + N_SPOTS)
#define N_EDGES 3200000
#define D 64
#define D4 (D / 4)

// Scratch (__device__ globals; allocations are forbidden).
// Combined node index space: [0, N_USERS) users, [N_USERS, N_NODES) spots.
__device__ int   g_deg[N_NODES];
__device__ float g_isq[N_NODES];
__device__ int   g_off[N_NODES];     // exclusive-scan start offsets
__device__ int   g_cursor[N_NODES];  // fill cursors; == end offsets after fill
__device__ int   g_adj[2 * N_EDGES]; // user lists then spot lists (combined scan)

__global__ void __launch_bounds__(256) zero_deg_kernel() {
    int i = blockIdx.x * blockDim.x + threadIdx.x;
    if (i < N_NODES) g_deg[i] = 0;
}

__global__ void __launch_bounds__(256) degree_kernel(const int* __restrict__ user_idx,
                                                     const int* __restrict__ spot_idx) {
    int e = blockIdx.x * blockDim.x + threadIdx.x;
    if (e < N_EDGES) {
        atomicAdd(&g_deg[user_idx[e]], 1);
        atomicAdd(&g_deg[N_USERS + spot_idx[e]], 1);
    }
}

// Single-block exclusive scan over g_deg -> g_off/g_cursor; also computes isq.
__global__ void __launch_bounds__(1024) scan_kernel() {
    __shared__ int partial[1024];
    const int tid = threadIdx.x;
    const int per = (N_NODES + 1023) / 1024;  // 245
    const int start = tid * per;
    const int end = min(start + per, N_NODES);

    int sum = 0;
    for (int i = start; i < end; ++i) sum += g_deg[i];
    partial[tid] = sum;
    __syncthreads();

    // Hillis-Steele inclusive scan
    for (int d = 1; d < 1024; d <<= 1) {
        int v = (tid >= d) ? partial[tid - d] : 0;
        __syncthreads();
        partial[tid] += v;
        __syncthreads();
    }
    int off = (tid == 0) ? 0 : partial[tid - 1];

    for (int i = start; i < end; ++i) {
        int dg = g_deg[i];
        g_off[i] = off;
        g_cursor[i] = off;
        float df = (float)dg;
        g_isq[i] = rsqrtf(dg == 0 ? 1e-6f : df);
        off += dg;
    }
}

__global__ void __launch_bounds__(256) fill_kernel(const int* __restrict__ user_idx,
                                                   const int* __restrict__ spot_idx) {
    int e = blockIdx.x * blockDim.x + threadIdx.x;
    if (e < N_EDGES) {
        int u = user_idx[e];
        int s = spot_idx[e];
        int pu = atomicAdd(&g_cursor[u], 1);
        g_adj[pu] = s;                         // user's list stores spot partner
        int ps = atomicAdd(&g_cursor[N_USERS + s], 1);
        g_adj[ps] = u;                         // spot's list stores user partner
    }
}

// One warp per node. Two half-warps process alternating edges (2 edges in
// flight), each of 16 lanes handles one float4 column chunk. Plain stores,
// zero atomics.
__global__ void __launch_bounds__(256) gather_kernel(const float* __restrict__ user_x,
                                                     const float* __restrict__ spot_x,
                                                     float* __restrict__ out) {
    int warp_id = (blockIdx.x * blockDim.x + threadIdx.x) >> 5;
    if (warp_id >= N_NODES) return;
    int n = warp_id;
    int lane = threadIdx.x & 31;
    int half = lane >> 4;
    int col = lane & 15;

    int start = g_off[n];
    int end = g_cursor[n];   // after fill, cursor sits at this node's end

    bool is_user = (n < N_USERS);
    const float4* px = (const float4*)(is_user ? spot_x : user_x);
    const float* isq_partner = is_user ? (g_isq + N_USERS) : g_isq;

    float4 acc = make_float4(0.f, 0.f, 0.f, 0.f);

    int i = start + half;
    // 2-deep software pipeline per half-warp (4 edges in flight per warp)
    for (; i + 2 < end; i += 4) {
        int p0 = __ldg(&g_adj[i]);
        int p1 = __ldg(&g_adj[i + 2]);
        float q0 = isq_partner[p0];
        float q1 = isq_partner[p1];
        float4 v0 = px[(long long)p0 * D4 + col];
        float4 v1 = px[(long long)p1 * D4 + col];
        acc.x += v0.x * q0; acc.y += v0.y * q0; acc.z += v0.z * q0; acc.w += v0.w * q0;
        acc.x += v1.x * q1; acc.y += v1.y * q1; acc.z += v1.z * q1; acc.w += v1.w * q1;
    }
    for (; i < end; i += 2) {
        int p = __ldg(&g_adj[i]);
        float q = isq_partner[p];
        float4 v = px[(long long)p * D4 + col];
        acc.x += v.x * q; acc.y += v.y * q; acc.z += v.z * q; acc.w += v.w * q;
    }

    // Combine the two half-warp partials (same columns, different edges).
    acc.x += __shfl_xor_sync(0xffffffffu, acc.x, 16);
    acc.y += __shfl_xor_sync(0xffffffffu, acc.y, 16);
    acc.z += __shfl_xor_sync(0xffffffffu, acc.z, 16);
    acc.w += __shfl_xor_sync(0xffffffffu, acc.w, 16);

    if (half == 0) {
        float isq_n = g_isq[n];
        float4 r = make_float4(acc.x * isq_n, acc.y * isq_n, acc.z * isq_n, acc.w * isq_n);
        // Output layout [user rows][spot rows] == combined node index * 64.
        ((float4*)out)[(long long)n * D4 + col] = r;
    }
}

extern "C" void kernel_launch(void* const* d_in, const int* in_sizes, int n_in,
                              void* d_out, int out_size) {
    const float* user_x   = (const float*)d_in[0];
    const float* spot_x   = (const float*)d_in[1];
    const int*   user_idx = (const int*)d_in[2];
    const int*   spot_idx = (const int*)d_in[3];
    float* out = (float*)d_out;

    zero_deg_kernel<<<(N_NODES + 255) / 256, 256>>>();
    degree_kernel<<<(N_EDGES + 255) / 256, 256>>>(user_idx, spot_idx);
    scan_kernel<<<1, 1024>>>();
    fill_kernel<<<(N_EDGES + 255) / 256, 256>>>(user_idx, spot_idx);

    long long gather_threads = (long long)N_NODES * 32;
    int gather_blocks = (int)((gather_threads + 255) / 256);
    gather_kernel<<<gather_blocks, 256>>>(user_x, spot_x, out);
}

// round 4
// speedup vs baseline: 3.0544x; 3.0544x over previous
#include <cuda_runtime.h>

#define N_USERS 200000
#define N_SPOTS 50000
#define N_NODES (N_USERS + N_SPOTS)
#define N_EDGES 3200000
#define D 64
#define D2 (D / 2)   // 32 float2 per row

// Scratch (__device__ globals; allocations forbidden).
// Combined node index space: [0, N_USERS) users, [N_USERS, N_NODES) spots.
__device__ int   g_deg[N_NODES];
__device__ float g_isq[N_NODES];
__device__ int   g_off[N_NODES];     // list start
__device__ int   g_cursor[N_NODES];  // fill cursor; == list end after fill
__device__ int   g_adj[2 * N_EDGES]; // partner indices (partner's LOCAL index)
__device__ int   g_ctr;              // bump allocator for offsets

__global__ void __launch_bounds__(256) zero_kernel() {
    int i = blockIdx.x * blockDim.x + threadIdx.x;
    if (i < N_NODES) g_deg[i] = 0;
    if (i == 0) g_ctr = 0;
}

__global__ void __launch_bounds__(256) degree_kernel(const int* __restrict__ user_idx,
                                                     const int* __restrict__ spot_idx) {
    int e = blockIdx.x * blockDim.x + threadIdx.x;
    if (e < N_EDGES) {
        atomicAdd(&g_deg[user_idx[e]], 1);
        atomicAdd(&g_deg[N_USERS + spot_idx[e]], 1);
    }
}

// Offsets via block scan + one global atomic per block. Region order across
// nodes is irrelevant — only disjoint contiguity matters.
__global__ void __launch_bounds__(1024) offsets_kernel() {
    __shared__ int sh[1024];
    __shared__ int base;
    int tid = threadIdx.x;
    int i = blockIdx.x * 1024 + tid;
    int dg = (i < N_NODES) ? g_deg[i] : 0;
    sh[tid] = dg;
    __syncthreads();
    #pragma unroll
    for (int d = 1; d < 1024; d <<= 1) {
        int v = (tid >= d) ? sh[tid - d] : 0;
        __syncthreads();
        sh[tid] += v;
        __syncthreads();
    }
    int incl = sh[tid];
    if (tid == 1023) base = atomicAdd(&g_ctr, sh[1023]);
    __syncthreads();
    if (i < N_NODES) {
        int off = base + incl - dg;
        g_off[i] = off;
        g_cursor[i] = off;
        g_isq[i] = rsqrtf(dg == 0 ? 1e-6f : (float)dg);
    }
}

__global__ void __launch_bounds__(256) fill_kernel(const int* __restrict__ user_idx,
                                                   const int* __restrict__ spot_idx) {
    int e = blockIdx.x * blockDim.x + threadIdx.x;
    if (e < N_EDGES) {
        int u = user_idx[e];
        int s = spot_idx[e];
        int pu = atomicAdd(&g_cursor[u], 1);
        g_adj[pu] = s;                 // user's list: spot partner (local idx)
        int ps = atomicAdd(&g_cursor[N_USERS + s], 1);
        g_adj[ps] = u;                 // spot's list: user partner
    }
}

// One warp per node; each lane owns one float2 column chunk; 8 edges in
// flight per iteration for deep MLP. Plain stores, zero atomics, no memset.
__global__ void __launch_bounds__(256) gather_kernel(const float* __restrict__ user_x,
                                                     const float* __restrict__ spot_x,
                                                     float* __restrict__ out) {
    int n = (blockIdx.x * blockDim.x + threadIdx.x) >> 5;
    if (n >= N_NODES) return;
    int lane = threadIdx.x & 31;

    int start = g_off[n];
    int end = g_cursor[n];

    bool is_user = (n < N_USERS);
    const float2* __restrict__ px = (const float2*)(is_user ? spot_x : user_x);
    const float* __restrict__ isqp = is_user ? (g_isq + N_USERS) : g_isq;

    float accx = 0.f, accy = 0.f;

    int i = start;
    for (; i + 8 <= end; i += 8) {
        int p[8];
        #pragma unroll
        for (int k = 0; k < 8; ++k) p[k] = __ldg(&g_adj[i + k]);
        float q[8];
        #pragma unroll
        for (int k = 0; k < 8; ++k) q[k] = __ldg(&isqp[p[k]]);
        float2 v[8];
        #pragma unroll
        for (int k = 0; k < 8; ++k) v[k] = __ldg(&px[p[k] * D2 + lane]);
        #pragma unroll
        for (int k = 0; k < 8; ++k) {
            accx += v[k].x * q[k];
            accy += v[k].y * q[k];
        }
    }
    for (; i < end; ++i) {
        int p = __ldg(&g_adj[i]);
        float q = __ldg(&isqp[p]);
        float2 v = __ldg(&px[p * D2 + lane]);
        accx += v.x * q;
        accy += v.y * q;
    }

    float s = g_isq[n];
    float2 r = make_float2(accx * s, accy * s);
    // Output layout [user rows][spot rows] == combined node index space.
    ((float2*)out)[n * D2 + lane] = r;
}

extern "C" void kernel_launch(void* const* d_in, const int* in_sizes, int n_in,
                              void* d_out, int out_size) {
    const float* user_x   = (const float*)d_in[0];
    const float* spot_x   = (const float*)d_in[1];
    const int*   user_idx = (const int*)d_in[2];
    const int*   spot_idx = (const int*)d_in[3];
    float* out = (float*)d_out;

    zero_kernel<<<(N_NODES + 255) / 256, 256>>>();
    degree_kernel<<<(N_EDGES + 255) / 256, 256>>>(user_idx, spot_idx);
    offsets_kernel<<<(N_NODES + 1023) / 1024, 1024>>>();
    fill_kernel<<<(N_EDGES + 255) / 256, 256>>>(user_idx, spot_idx);

    long long gather_threads = (long long)N_NODES * 32;
    int gather_blocks = (int)((gather_threads + 255) / 256);
    gather_kernel<<<gather_blocks, 256>>>(user_x, spot_x, out);
}